// round 2
// baseline (speedup 1.0000x reference)
#include <cuda_runtime.h>

#define T_STEPS 28
#define HID 128
#define IND 28
#define NCLS 10
#define BATCH 8192
#define RPB 32   // batch rows per block (= warp lanes)

typedef unsigned long long u64;

// 112 MB scratch for precomputed layer-0 input GEMM (+ fused biases)
__device__ float g_xw0[BATCH * T_STEPS * HID];

// packed fp32x2 FMA: acc = a*b + acc  (2 fp32 lanes per instruction)
#define FMA2(acc, a, b) \
    asm("fma.rn.f32x2 %0, %1, %2, %0;" : "+l"(acc) : "l"(a), "l"(b))
// duplicate a scalar float into both halves of a 64-bit packed reg
#define DUP2(d, s) \
    asm("mov.b64 %0, {%1, %1};" : "=l"(d) : "f"(s))
// unpack
#define UNPK2(lo, hi, p) \
    asm("mov.b64 {%0, %1}, %2;" : "=f"(lo), "=f"(hi) : "l"(p))
// 16B shared load as two packed u64 (two (f32,f32) pairs)
#define LDS2(a, b, addr) \
    asm("ld.shared.v2.u64 {%0, %1}, [%2];" : "=l"(a), "=l"(b) : "r"(addr))
// 16B global load as two packed u64
#define LDG2(a, b, p) \
    asm("ld.global.nc.v2.u64 {%0, %1}, [%2];" : "=l"(a), "=l"(b) : "l"(p))
// 16B global store from two packed u64
#define STG2(p, a, b) \
    asm("st.global.v2.u64 [%0], {%1, %2};" :: "l"(p), "l"(a), "l"(b))

__device__ __forceinline__ float ftanh(float x) {
    // tanh(x) = 1 - 2/(e^{2x}+1); saturates correctly at +/-inf, no NaN.
    float e = __expf(2.0f * x);
    return 1.0f - __fdividef(2.0f, e + 1.0f);
}

__device__ __forceinline__ unsigned smaddr(const void* p) {
    return (unsigned)__cvta_generic_to_shared(p);
}

// ---------------------------------------------------------------------------
// Kernel 1: xw0[b,t,:] = x[b,t,:] @ W_ih0^T + (b_ih0 + b_hh0)
// 32 flattened rows/block. lane = row, warp w = cols 16w..16w+15.
// ---------------------------------------------------------------------------
__global__ __launch_bounds__(256, 1) void input_gemm_kernel(
    const float* __restrict__ x, const float* __restrict__ Wih0,
    const float* __restrict__ bih0, const float* __restrict__ bhh0)
{
    __shared__ float Wt[IND * HID];    // Wt[d][j]
    __shared__ float xs[RPB * 29];     // pad 28->29 (odd stride, no conflicts)
    __shared__ float bs[HID];

    const int tid = threadIdx.x;
    const int r0 = blockIdx.x * RPB;

    for (int idx = tid; idx < HID * IND; idx += 256) {
        int j = idx / IND, d = idx - j * IND;
        Wt[d * HID + j] = Wih0[idx];
    }
    if (tid < HID) bs[tid] = bih0[tid] + bhh0[tid];
    for (int idx = tid; idx < RPB * IND; idx += 256) {
        int r = idx / IND, d = idx - r * IND;
        xs[r * 29 + d] = x[r0 * IND + idx];     // rows contiguous in x
    }
    __syncthreads();

    const int w = tid >> 5, lane = tid & 31;
    const int col0 = 16 * w;

    const unsigned aW = smaddr(Wt) + col0 * 4;
    const unsigned aB = smaddr(bs) + col0 * 4;

    u64 acc[8];
    LDS2(acc[0], acc[1], aB);
    LDS2(acc[2], acc[3], aB + 16);
    LDS2(acc[4], acc[5], aB + 32);
    LDS2(acc[6], acc[7], aB + 48);

#pragma unroll
    for (int d = 0; d < IND; d++) {
        float h = xs[lane * 29 + d];
        u64 hh; DUP2(hh, h);
        u64 w0, w1, w2, w3, w4, w5, w6, w7;
        LDS2(w0, w1, aW + d * 512);
        LDS2(w2, w3, aW + d * 512 + 16);
        LDS2(w4, w5, aW + d * 512 + 32);
        LDS2(w6, w7, aW + d * 512 + 48);
        FMA2(acc[0], hh, w0); FMA2(acc[1], hh, w1);
        FMA2(acc[2], hh, w2); FMA2(acc[3], hh, w3);
        FMA2(acc[4], hh, w4); FMA2(acc[5], hh, w5);
        FMA2(acc[6], hh, w6); FMA2(acc[7], hh, w7);
    }

    float* dst = &g_xw0[(r0 + lane) * HID + col0];
    STG2((u64)dst,        acc[0], acc[1]);
    STG2((u64)dst + 16,   acc[2], acc[3]);
    STG2((u64)dst + 32,   acc[4], acc[5]);
    STG2((u64)dst + 48,   acc[6], acc[7]);
}

// ---------------------------------------------------------------------------
// Kernel 2: fused 2-layer recurrence + FC head.
// lane = batch row (32 rows/CTA), warp w = hidden cols 16w..16w+15.
// h arrays stored transposed [k][row] so h-loads are coalesced and weight
// loads are pure warp-broadcast. All math in packed fp32x2.
// ---------------------------------------------------------------------------
__global__ __launch_bounds__(256, 1) void rnn_main_kernel(
    const float* __restrict__ Whh0, const float* __restrict__ Wih1,
    const float* __restrict__ Whh1, const float* __restrict__ bih1,
    const float* __restrict__ bhh1, const float* __restrict__ fcw,
    const float* __restrict__ fcb, float* __restrict__ out)
{
    extern __shared__ float sm[];
    float* W0  = sm;             // Whh0^T [k][j] 128x128
    float* W1  = sm + 16384;     // Wih1^T
    float* W2  = sm + 32768;     // Whh1^T
    float* h0T = sm + 49152;     // [k][row] 128x32
    float* h1T = sm + 53248;     // [k][row] 128x32
    float* b1s = sm + 57344;     // [128]
    // total 57472 floats = 229,888 B

    const int tid = threadIdx.x;
    const int b0 = blockIdx.x * RPB;

    for (int idx = tid; idx < HID * HID; idx += 256) {
        int j = idx >> 7, k = idx & 127;
        W0[k * HID + j] = Whh0[idx];
        W1[k * HID + j] = Wih1[idx];
        W2[k * HID + j] = Whh1[idx];
    }
    for (int idx = tid; idx < RPB * HID; idx += 256) {
        h0T[idx] = 0.0f; h1T[idx] = 0.0f;
    }
    if (tid < HID) b1s[tid] = bih1[tid] + bhh1[tid];
    __syncthreads();

    const int w = tid >> 5, lane = tid & 31;
    const int col0 = 16 * w;

    const unsigned aW0 = smaddr(W0)  + col0 * 4;
    const unsigned aW1 = smaddr(W1)  + col0 * 4;
    const unsigned aW2 = smaddr(W2)  + col0 * 4;
    const unsigned aB1 = smaddr(b1s) + col0 * 4;

    // prefetch xw0 for t=0: 16 floats = 8 packed pairs
    const float* xwp = &g_xw0[((b0 + lane) * T_STEPS + 0) * HID + col0];
    u64 xp[8];
    LDG2(xp[0], xp[1], (u64)xwp);
    LDG2(xp[2], xp[3], (u64)xwp + 16);
    LDG2(xp[4], xp[5], (u64)xwp + 32);
    LDG2(xp[6], xp[7], (u64)xwp + 48);

    for (int t = 0; t < T_STEPS; t++) {
        u64 acc[8];
#pragma unroll
        for (int j = 0; j < 8; j++) acc[j] = xp[j];

        if (t + 1 < T_STEPS) {
            const float* nx = &g_xw0[((b0 + lane) * T_STEPS + (t + 1)) * HID + col0];
            LDG2(xp[0], xp[1], (u64)nx);
            LDG2(xp[2], xp[3], (u64)nx + 16);
            LDG2(xp[4], xp[5], (u64)nx + 32);
            LDG2(xp[6], xp[7], (u64)nx + 48);
        }

        // ---- layer 0: acc += h0 @ Whh0^T ----
#pragma unroll 8
        for (int k = 0; k < HID; k++) {
            float h = h0T[k * RPB + lane];
            u64 hh; DUP2(hh, h);
            u64 w0, w1, w2, w3, w4, w5, w6, w7;
            LDS2(w0, w1, aW0 + k * 512);
            LDS2(w2, w3, aW0 + k * 512 + 16);
            LDS2(w4, w5, aW0 + k * 512 + 32);
            LDS2(w6, w7, aW0 + k * 512 + 48);
            FMA2(acc[0], hh, w0); FMA2(acc[1], hh, w1);
            FMA2(acc[2], hh, w2); FMA2(acc[3], hh, w3);
            FMA2(acc[4], hh, w4); FMA2(acc[5], hh, w5);
            FMA2(acc[6], hh, w6); FMA2(acc[7], hh, w7);
        }

        float hn[16];
#pragma unroll
        for (int j = 0; j < 8; j++) {
            float lo, hi; UNPK2(lo, hi, acc[j]);
            hn[2 * j] = ftanh(lo); hn[2 * j + 1] = ftanh(hi);
        }
        __syncthreads();                       // readers of old h0 done
#pragma unroll
        for (int j = 0; j < 16; j++) h0T[(col0 + j) * RPB + lane] = hn[j];
        __syncthreads();                       // new h0 visible

        // ---- layer 1: acc = b1 + h0_new @ Wih1^T + h1 @ Whh1^T ----
        LDS2(acc[0], acc[1], aB1);
        LDS2(acc[2], acc[3], aB1 + 16);
        LDS2(acc[4], acc[5], aB1 + 32);
        LDS2(acc[6], acc[7], aB1 + 48);

#pragma unroll 4
        for (int k = 0; k < HID; k++) {
            float a = h0T[k * RPB + lane];
            float b = h1T[k * RPB + lane];
            u64 aa, bb; DUP2(aa, a); DUP2(bb, b);
            u64 p0, p1, p2, p3, p4, p5, p6, p7;
            LDS2(p0, p1, aW1 + k * 512);
            LDS2(p2, p3, aW1 + k * 512 + 16);
            LDS2(p4, p5, aW1 + k * 512 + 32);
            LDS2(p6, p7, aW1 + k * 512 + 48);
            FMA2(acc[0], aa, p0); FMA2(acc[1], aa, p1);
            FMA2(acc[2], aa, p2); FMA2(acc[3], aa, p3);
            FMA2(acc[4], aa, p4); FMA2(acc[5], aa, p5);
            FMA2(acc[6], aa, p6); FMA2(acc[7], aa, p7);
            LDS2(p0, p1, aW2 + k * 512);
            LDS2(p2, p3, aW2 + k * 512 + 16);
            LDS2(p4, p5, aW2 + k * 512 + 32);
            LDS2(p6, p7, aW2 + k * 512 + 48);
            FMA2(acc[0], bb, p0); FMA2(acc[1], bb, p1);
            FMA2(acc[2], bb, p2); FMA2(acc[3], bb, p3);
            FMA2(acc[4], bb, p4); FMA2(acc[5], bb, p5);
            FMA2(acc[6], bb, p6); FMA2(acc[7], bb, p7);
        }

#pragma unroll
        for (int j = 0; j < 8; j++) {
            float lo, hi; UNPK2(lo, hi, acc[j]);
            hn[2 * j] = ftanh(lo); hn[2 * j + 1] = ftanh(hi);
        }
        __syncthreads();                       // readers of old h1 done
#pragma unroll
        for (int j = 0; j < 16; j++) h1T[(col0 + j) * RPB + lane] = hn[j];
        __syncthreads();                       // new h1 visible
    }

    // ---- FC head: out = h1 @ fc_w^T + fc_b (stage fc_w in freed W0) ----
    for (int idx = tid; idx < NCLS * HID; idx += 256) W0[idx] = fcw[idx];
    if (tid < NCLS) b1s[tid] = fcb[tid];
    __syncthreads();

    for (int idx = tid; idx < RPB * NCLS; idx += 256) {
        int m = idx / NCLS, c = idx - m * NCLS;
        float a = b1s[c];
#pragma unroll 8
        for (int k = 0; k < HID; k++)
            a += h1T[k * RPB + m] * W0[c * HID + k];
        out[(b0 + m) * NCLS + c] = a;
    }
}

// ---------------------------------------------------------------------------
extern "C" void kernel_launch(void* const* d_in, const int* in_sizes, int n_in,
                              void* d_out, int out_size) {
    const float* x    = (const float*)d_in[0];
    const float* Wih0 = (const float*)d_in[1];
    const float* Whh0 = (const float*)d_in[2];
    const float* bih0 = (const float*)d_in[3];
    const float* bhh0 = (const float*)d_in[4];
    const float* Wih1 = (const float*)d_in[5];
    const float* Whh1 = (const float*)d_in[6];
    const float* bih1 = (const float*)d_in[7];
    const float* bhh1 = (const float*)d_in[8];
    const float* fcw  = (const float*)d_in[9];
    const float* fcb  = (const float*)d_in[10];
    float* out = (float*)d_out;

    cudaFuncSetAttribute(rnn_main_kernel,
                         cudaFuncAttributeMaxDynamicSharedMemorySize, 229888);

    input_gemm_kernel<<<(BATCH * T_STEPS) / RPB, 256>>>(x, Wih0, bih0, bhh0);
    rnn_main_kernel<<<BATCH / RPB, 256, 229888>>>(Whh0, Wih1, Whh1,
                                                  bih1, bhh1, fcw, fcb, out);
}

// round 3
// speedup vs baseline: 1.2786x; 1.2786x over previous
#include <cuda_runtime.h>

#define T_STEPS 28
#define HID 128
#define IND 28
#define NCLS 10
#define BATCH 8192
#define RPB 64              // batch rows per CTA (main kernel)
#define IG_GROUPS 4
#define IG_RPB (64 * IG_GROUPS)

typedef unsigned long long u64;

// scratch: precomputed layer-0 input GEMM (+ fused biases), transposed Whh1
__device__ float g_xw0[BATCH * T_STEPS * HID];
__device__ float g_W2T[HID * HID];

// packed fp32x2 FMA: acc = a*b + acc
#define FMA2(acc, a, b) \
    asm("fma.rn.f32x2 %0, %1, %2, %0;" : "+l"(acc) : "l"(a), "l"(b))
#define DUP2(d, s) \
    asm("mov.b64 %0, {%1, %1};" : "=l"(d) : "f"(s))
#define UNPK2(lo, hi, p) \
    asm("mov.b64 {%0, %1}, %2;" : "=f"(lo), "=f"(hi) : "l"(p))
#define LDS2(a, b, addr) \
    asm("ld.shared.v2.u64 {%0, %1}, [%2];" : "=l"(a), "=l"(b) : "r"(addr))
#define LDG2(a, b, p) \
    asm("ld.global.nc.v2.u64 {%0, %1}, [%2];" : "=l"(a), "=l"(b) : "l"(p))
#define STG2(p, a, b) \
    asm("st.global.v2.u64 [%0], {%1, %2};" :: "l"(p), "l"(a), "l"(b))

__device__ __forceinline__ float ftanh(float x) {
    float e = __expf(2.0f * x);
    return 1.0f - __fdividef(2.0f, e + 1.0f);
}
__device__ __forceinline__ unsigned smaddr(const void* p) {
    return (unsigned)__cvta_generic_to_shared(p);
}

// ---------------------------------------------------------------------------
// Tiny kernel: g_W2T[k][j] = Whh1[j][k]
// ---------------------------------------------------------------------------
__global__ void transpose_w2_kernel(const float* __restrict__ Whh1) {
    int idx = blockIdx.x * 256 + threadIdx.x;   // grid 64 -> 16384 elems
    int j = idx >> 7, k = idx & 127;
    g_W2T[k * HID + j] = Whh1[idx];
}

// ---------------------------------------------------------------------------
// Kernel 1: xw0[r,:] = x[r,:] @ W_ih0^T + (b_ih0+b_hh0), r = flattened (b,t).
// 256 rows per CTA in 4 groups of 64; lane owns rows (2*lane, 2*lane+1) of
// the group, warp w owns output cols 16w..16w+15. Packed f32x2 math.
// ---------------------------------------------------------------------------
__global__ __launch_bounds__(256, 1) void input_gemm_kernel(
    const float* __restrict__ x, const float* __restrict__ Wih0,
    const float* __restrict__ bih0, const float* __restrict__ bhh0)
{
    __shared__ float Wt[IND * HID];    // Wt[d][j]
    __shared__ float xsT[IND * 64];    // [d][row] for current 64-row group
    __shared__ float bs[HID];

    const int tid = threadIdx.x;
    const int w = tid >> 5, lane = tid & 31;
    const int col0 = 16 * w, r0 = 2 * lane;

    for (int idx = tid; idx < HID * IND; idx += 256) {
        int j = idx / IND, d = idx - j * IND;
        Wt[d * HID + j] = Wih0[idx];
    }
    if (tid < HID) bs[tid] = bih0[tid] + bhh0[tid];
    __syncthreads();

    const unsigned aW = smaddr(Wt) + col0 * 4;
    const unsigned aB = smaddr(bs) + col0 * 4;

    for (int g = 0; g < IG_GROUPS; g++) {
        const int gr0 = blockIdx.x * IG_RPB + g * 64;
        __syncthreads();                       // xsT free to overwrite
        for (int idx = tid; idx < 64 * IND; idx += 256) {
            int r = idx / IND, d = idx - r * IND;
            xsT[d * 64 + r] = x[gr0 * IND + idx];   // rows contiguous in x
        }
        __syncthreads();

        u64 acc0[8], acc1[8];
        LDS2(acc0[0], acc0[1], aB);
        LDS2(acc0[2], acc0[3], aB + 16);
        LDS2(acc0[4], acc0[5], aB + 32);
        LDS2(acc0[6], acc0[7], aB + 48);
#pragma unroll
        for (int j = 0; j < 8; j++) acc1[j] = acc0[j];

#pragma unroll
        for (int d = 0; d < IND; d++) {
            float2 hp = *(const float2*)&xsT[d * 64 + r0];
            u64 ha, hb; DUP2(ha, hp.x); DUP2(hb, hp.y);
            u64 w0, w1, w2, w3, w4, w5, w6, w7;
            LDS2(w0, w1, aW + d * 512);
            LDS2(w2, w3, aW + d * 512 + 16);
            LDS2(w4, w5, aW + d * 512 + 32);
            LDS2(w6, w7, aW + d * 512 + 48);
            FMA2(acc0[0], ha, w0); FMA2(acc0[1], ha, w1);
            FMA2(acc0[2], ha, w2); FMA2(acc0[3], ha, w3);
            FMA2(acc0[4], ha, w4); FMA2(acc0[5], ha, w5);
            FMA2(acc0[6], ha, w6); FMA2(acc0[7], ha, w7);
            FMA2(acc1[0], hb, w0); FMA2(acc1[1], hb, w1);
            FMA2(acc1[2], hb, w2); FMA2(acc1[3], hb, w3);
            FMA2(acc1[4], hb, w4); FMA2(acc1[5], hb, w5);
            FMA2(acc1[6], hb, w6); FMA2(acc1[7], hb, w7);
        }

        float* dst0 = &g_xw0[(gr0 + r0) * HID + col0];
        float* dst1 = dst0 + HID;
        STG2((u64)dst0,      acc0[0], acc0[1]);
        STG2((u64)dst0 + 16, acc0[2], acc0[3]);
        STG2((u64)dst0 + 32, acc0[4], acc0[5]);
        STG2((u64)dst0 + 48, acc0[6], acc0[7]);
        STG2((u64)dst1,      acc1[0], acc1[1]);
        STG2((u64)dst1 + 16, acc1[2], acc1[3]);
        STG2((u64)dst1 + 32, acc1[4], acc1[5]);
        STG2((u64)dst1 + 48, acc1[6], acc1[7]);
    }
}

// ---------------------------------------------------------------------------
// Kernel 2: fused 2-layer recurrence + FC head.
// 64 batch rows/CTA: lane owns rows (2*lane, 2*lane+1), warp w owns hidden
// cols 16w..16w+15. h stored transposed [k][row]. Whh0/Wih1 in smem,
// Whh1 streamed from global (pre-transposed). All math packed fp32x2.
// ---------------------------------------------------------------------------
__global__ __launch_bounds__(256, 1) void rnn_main_kernel(
    const float* __restrict__ Whh0, const float* __restrict__ Wih1,
    const float* __restrict__ bih1, const float* __restrict__ bhh1,
    const float* __restrict__ fcw,  const float* __restrict__ fcb,
    float* __restrict__ out)
{
    extern __shared__ float sm[];
    float* W0  = sm;              // Whh0^T [k][j] 128x128
    float* W1  = sm + 16384;      // Wih1^T
    float* h0T = sm + 32768;      // [k][row] 128x64
    float* h1T = sm + 40960;      // [k][row] 128x64
    float* b1s = sm + 49152;      // [128]
    // total 49280 floats = 197,120 B

    const int tid = threadIdx.x;
    const int b0 = blockIdx.x * RPB;

    for (int idx = tid; idx < HID * HID; idx += 256) {
        int j = idx >> 7, k = idx & 127;
        W0[k * HID + j] = Whh0[idx];
        W1[k * HID + j] = Wih1[idx];
    }
    for (int idx = tid; idx < RPB * HID; idx += 256) {
        h0T[idx] = 0.0f; h1T[idx] = 0.0f;
    }
    if (tid < HID) b1s[tid] = bih1[tid] + bhh1[tid];
    __syncthreads();

    const int w = tid >> 5, lane = tid & 31;
    const int col0 = 16 * w, r0 = 2 * lane;

    const unsigned aW0 = smaddr(W0)  + col0 * 4;
    const unsigned aW1 = smaddr(W1)  + col0 * 4;
    const unsigned aB1 = smaddr(b1s) + col0 * 4;
    const unsigned aH0 = smaddr(h0T) + r0 * 4;
    const unsigned aH1 = smaddr(h1T) + r0 * 4;
    const float* pW2 = g_W2T + col0;

    // prefetch xw0 for t=0 (rows r0, r0+1)
    const float* xq0 = &g_xw0[((b0 + r0) * T_STEPS + 0) * HID + col0];
    u64 xp0[8], xp1[8];
    LDG2(xp0[0], xp0[1], (u64)xq0);
    LDG2(xp0[2], xp0[3], (u64)xq0 + 16);
    LDG2(xp0[4], xp0[5], (u64)xq0 + 32);
    LDG2(xp0[6], xp0[7], (u64)xq0 + 48);
    const float* xq1 = xq0 + T_STEPS * HID;
    LDG2(xp1[0], xp1[1], (u64)xq1);
    LDG2(xp1[2], xp1[3], (u64)xq1 + 16);
    LDG2(xp1[4], xp1[5], (u64)xq1 + 32);
    LDG2(xp1[6], xp1[7], (u64)xq1 + 48);

    for (int t = 0; t < T_STEPS; t++) {
        u64 acc0[8], acc1[8];
#pragma unroll
        for (int j = 0; j < 8; j++) { acc0[j] = xp0[j]; acc1[j] = xp1[j]; }

        // ---- layer 0: acc += h0 @ Whh0^T ----
#pragma unroll 4
        for (int k = 0; k < HID; k++) {
            float2 hp; asm("ld.shared.v2.f32 {%0,%1}, [%2];"
                           : "=f"(hp.x), "=f"(hp.y) : "r"(aH0 + k * 256));
            u64 ha, hb; DUP2(ha, hp.x); DUP2(hb, hp.y);
            u64 w0, w1, w2, w3, w4, w5, w6, w7;
            LDS2(w0, w1, aW0 + k * 512);
            LDS2(w2, w3, aW0 + k * 512 + 16);
            LDS2(w4, w5, aW0 + k * 512 + 32);
            LDS2(w6, w7, aW0 + k * 512 + 48);
            FMA2(acc0[0], ha, w0); FMA2(acc0[1], ha, w1);
            FMA2(acc0[2], ha, w2); FMA2(acc0[3], ha, w3);
            FMA2(acc0[4], ha, w4); FMA2(acc0[5], ha, w5);
            FMA2(acc0[6], ha, w6); FMA2(acc0[7], ha, w7);
            FMA2(acc1[0], hb, w0); FMA2(acc1[1], hb, w1);
            FMA2(acc1[2], hb, w2); FMA2(acc1[3], hb, w3);
            FMA2(acc1[4], hb, w4); FMA2(acc1[5], hb, w5);
            FMA2(acc1[6], hb, w6); FMA2(acc1[7], hb, w7);
        }

        float hn0[16], hn1[16];
#pragma unroll
        for (int j = 0; j < 8; j++) {
            float lo, hi;
            UNPK2(lo, hi, acc0[j]); hn0[2*j] = ftanh(lo); hn0[2*j+1] = ftanh(hi);
            UNPK2(lo, hi, acc1[j]); hn1[2*j] = ftanh(lo); hn1[2*j+1] = ftanh(hi);
        }
        __syncthreads();                        // readers of old h0 done
#pragma unroll
        for (int j = 0; j < 16; j++)
            *(float2*)&h0T[(col0 + j) * RPB + r0] = make_float2(hn0[j], hn1[j]);
        __syncthreads();                        // new h0 visible

        // ---- layer 1: acc = b1 + h0_new @ Wih1^T + h1 @ Whh1^T ----
        LDS2(acc0[0], acc0[1], aB1);
        LDS2(acc0[2], acc0[3], aB1 + 16);
        LDS2(acc0[4], acc0[5], aB1 + 32);
        LDS2(acc0[6], acc0[7], aB1 + 48);
#pragma unroll
        for (int j = 0; j < 8; j++) acc1[j] = acc0[j];

        if (t + 1 < T_STEPS) {                  // prefetch next step's xw0
            const float* n0 = &g_xw0[((b0 + r0) * T_STEPS + t + 1) * HID + col0];
            LDG2(xp0[0], xp0[1], (u64)n0);
            LDG2(xp0[2], xp0[3], (u64)n0 + 16);
            LDG2(xp0[4], xp0[5], (u64)n0 + 32);
            LDG2(xp0[6], xp0[7], (u64)n0 + 48);
            const float* n1 = n0 + T_STEPS * HID;
            LDG2(xp1[0], xp1[1], (u64)n1);
            LDG2(xp1[2], xp1[3], (u64)n1 + 16);
            LDG2(xp1[4], xp1[5], (u64)n1 + 32);
            LDG2(xp1[6], xp1[7], (u64)n1 + 48);
        }

#pragma unroll 2
        for (int k = 0; k < HID; k++) {
            float2 ap; asm("ld.shared.v2.f32 {%0,%1}, [%2];"
                           : "=f"(ap.x), "=f"(ap.y) : "r"(aH0 + k * 256));
            float2 bp; asm("ld.shared.v2.f32 {%0,%1}, [%2];"
                           : "=f"(bp.x), "=f"(bp.y) : "r"(aH1 + k * 256));
            u64 aa, ab, ba, bb;
            DUP2(aa, ap.x); DUP2(ab, ap.y); DUP2(ba, bp.x); DUP2(bb, bp.y);
            u64 p0, p1, p2, p3, p4, p5, p6, p7;
            LDS2(p0, p1, aW1 + k * 512);
            LDS2(p2, p3, aW1 + k * 512 + 16);
            LDS2(p4, p5, aW1 + k * 512 + 32);
            LDS2(p6, p7, aW1 + k * 512 + 48);
            FMA2(acc0[0], aa, p0); FMA2(acc0[1], aa, p1);
            FMA2(acc0[2], aa, p2); FMA2(acc0[3], aa, p3);
            FMA2(acc0[4], aa, p4); FMA2(acc0[5], aa, p5);
            FMA2(acc0[6], aa, p6); FMA2(acc0[7], aa, p7);
            FMA2(acc1[0], ab, p0); FMA2(acc1[1], ab, p1);
            FMA2(acc1[2], ab, p2); FMA2(acc1[3], ab, p3);
            FMA2(acc1[4], ab, p4); FMA2(acc1[5], ab, p5);
            FMA2(acc1[6], ab, p6); FMA2(acc1[7], ab, p7);
            const u64 gW2 = (u64)(pW2 + k * HID);
            LDG2(p0, p1, gW2);
            LDG2(p2, p3, gW2 + 16);
            LDG2(p4, p5, gW2 + 32);
            LDG2(p6, p7, gW2 + 48);
            FMA2(acc0[0], ba, p0); FMA2(acc0[1], ba, p1);
            FMA2(acc0[2], ba, p2); FMA2(acc0[3], ba, p3);
            FMA2(acc0[4], ba, p4); FMA2(acc0[5], ba, p5);
            FMA2(acc0[6], ba, p6); FMA2(acc0[7], ba, p7);
            FMA2(acc1[0], bb, p0); FMA2(acc1[1], bb, p1);
            FMA2(acc1[2], bb, p2); FMA2(acc1[3], bb, p3);
            FMA2(acc1[4], bb, p4); FMA2(acc1[5], bb, p5);
            FMA2(acc1[6], bb, p6); FMA2(acc1[7], bb, p7);
        }

#pragma unroll
        for (int j = 0; j < 8; j++) {
            float lo, hi;
            UNPK2(lo, hi, acc0[j]); hn0[2*j] = ftanh(lo); hn0[2*j+1] = ftanh(hi);
            UNPK2(lo, hi, acc1[j]); hn1[2*j] = ftanh(lo); hn1[2*j+1] = ftanh(hi);
        }
        __syncthreads();                        // readers of old h1 done
#pragma unroll
        for (int j = 0; j < 16; j++)
            *(float2*)&h1T[(col0 + j) * RPB + r0] = make_float2(hn0[j], hn1[j]);
        __syncthreads();                        // new h1 visible
    }

    // ---- FC head: out = h1 @ fc_w^T + fc_b (stage fc_w in freed W0) ----
    for (int idx = tid; idx < NCLS * HID; idx += 256) W0[idx] = fcw[idx];
    if (tid < NCLS) b1s[tid] = fcb[tid];
    __syncthreads();

    for (int idx = tid; idx < RPB * NCLS; idx += 256) {
        int m = idx / NCLS, c = idx - m * NCLS;
        float a = b1s[c];
#pragma unroll 8
        for (int k = 0; k < HID; k++)
            a += h1T[k * RPB + m] * W0[c * HID + k];
        out[(b0 + m) * NCLS + c] = a;
    }
}

// ---------------------------------------------------------------------------
extern "C" void kernel_launch(void* const* d_in, const int* in_sizes, int n_in,
                              void* d_out, int out_size) {
    const float* x    = (const float*)d_in[0];
    const float* Wih0 = (const float*)d_in[1];
    const float* Whh0 = (const float*)d_in[2];
    const float* bih0 = (const float*)d_in[3];
    const float* bhh0 = (const float*)d_in[4];
    const float* Wih1 = (const float*)d_in[5];
    const float* Whh1 = (const float*)d_in[6];
    const float* bih1 = (const float*)d_in[7];
    const float* bhh1 = (const float*)d_in[8];
    const float* fcw  = (const float*)d_in[9];
    const float* fcb  = (const float*)d_in[10];
    float* out = (float*)d_out;

    cudaFuncSetAttribute(rnn_main_kernel,
                         cudaFuncAttributeMaxDynamicSharedMemorySize, 197120);

    transpose_w2_kernel<<<64, 256>>>(Whh1);
    input_gemm_kernel<<<(BATCH * T_STEPS) / IG_RPB, 256>>>(x, Wih0, bih0, bhh0);
    rnn_main_kernel<<<BATCH / RPB, 256, 197120>>>(Whh0, Wih1, bih1, bhh1,
                                                  fcw, fcb, out);
}

// round 7
// speedup vs baseline: 2.7594x; 2.1581x over previous
#include <cuda_runtime.h>
#include <cuda_bf16.h>
#include <cstdint>

#define T_STEPS 28
#define HID 128
#define IND 28
#define NCLS 10
#define BATCH 8192
#define IG_GROUPS 4
#define IG_RPB (64 * IG_GROUPS)

typedef unsigned long long u64;

// 112 MB scratch: precomputed layer-0 input GEMM (+ fused biases)
__device__ float g_xw0[BATCH * T_STEPS * HID];

// ---------------- packed fp32x2 helpers (input gemm) ----------------
#define FMA2(acc, a, b) \
    asm("fma.rn.f32x2 %0, %1, %2, %0;" : "+l"(acc) : "l"(a), "l"(b))
#define DUP2(d, s) \
    asm("mov.b64 %0, {%1, %1};" : "=l"(d) : "f"(s))
#define LDS2(a, b, addr) \
    asm("ld.shared.v2.u64 {%0, %1}, [%2];" : "=l"(a), "=l"(b) : "r"(addr))
#define STG2(p, a, b) \
    asm("st.global.v2.u64 [%0], {%1, %2};" :: "l"(p), "l"(a), "l"(b))

__device__ __forceinline__ float ftanh(float x) {
    float e = __expf(2.0f * x);
    return 1.0f - __fdividef(2.0f, e + 1.0f);
}
__device__ __forceinline__ unsigned smaddr(const void* p) {
    return (unsigned)__cvta_generic_to_shared(p);
}

// ---------------- mma.sync helpers (compute_103-safe) ----------------
__device__ __forceinline__ void ldsm4(uint32_t* r, uint32_t a) {
    asm volatile("ldmatrix.sync.aligned.m8n8.x4.shared.b16 {%0,%1,%2,%3}, [%4];"
                 : "=r"(r[0]), "=r"(r[1]), "=r"(r[2]), "=r"(r[3]) : "r"(a));
}
__device__ __forceinline__ void mma16816(float* d, const uint32_t* a,
                                         uint32_t b0, uint32_t b1) {
    asm volatile("mma.sync.aligned.m16n8k16.row.col.f32.bf16.bf16.f32 "
                 "{%0,%1,%2,%3}, {%4,%5,%6,%7}, {%8,%9}, {%0,%1,%2,%3};"
                 : "+f"(d[0]), "+f"(d[1]), "+f"(d[2]), "+f"(d[3])
                 : "r"(a[0]), "r"(a[1]), "r"(a[2]), "r"(a[3]), "r"(b0), "r"(b1));
}
// pack two f32 into bf16x2: lower = v0, upper = v1
__device__ __forceinline__ uint32_t pack2(float v0, float v1) {
    uint32_t r;
    asm("cvt.rn.bf16x2.f32 %0, %1, %2;" : "=r"(r) : "f"(v1), "f"(v0));
    return r;
}
// value pair -> (hi bf16x2, lo bf16x2 residual)
__device__ __forceinline__ void cvt_pair(float v0, float v1,
                                         uint32_t& hi, uint32_t& lo) {
    uint32_t hp = pack2(v0, v1);
    float e0 = __uint_as_float(hp << 16);
    float e1 = __uint_as_float(hp & 0xffff0000u);
    hi = hp;
    lo = pack2(v0 - e0, v1 - e1);
}

// weight tile geometry: [n][k] bf16, row padded to 272 B (conflict-free LDSM)
#define WROW 272
#define WTILE (128 * WROW)        // 34816 B

// smem offsets (dynamic)
#define SM_W    0                 // 6 tiles: W0h W0l W1h W1l W2h W2l
#define SM_B1   (6 * WTILE)       // 208896: 128 f32
#define SM_FCW  (SM_B1 + 512)     // 209408: 1280 f32
#define SM_FCB  (SM_FCW + 5120)   // 214528: 16 f32
#define SMEM_TOTAL 214656

// 3-term split-bf16 GEMM: d[16][4] += A(split) @ W(split)^T, K=128
__device__ __forceinline__ void gemm3(float (*d)[4],
                                      const uint32_t (*ah)[4],
                                      const uint32_t (*al)[4],
                                      uint32_t baseHi, uint32_t baseLo) {
#pragma unroll
    for (int s = 0; s < 8; s++) {
#pragma unroll
        for (int j = 0; j < 8; j++) {
            uint32_t bh[4], bl[4];
            ldsm4(bh, baseHi + j * (16 * WROW) + s * 32);
            ldsm4(bl, baseLo + j * (16 * WROW) + s * 32);
            mma16816(d[2 * j],     ah[s], bh[0], bh[1]);
            mma16816(d[2 * j + 1], ah[s], bh[2], bh[3]);
            mma16816(d[2 * j],     ah[s], bl[0], bl[1]);
            mma16816(d[2 * j + 1], ah[s], bl[2], bl[3]);
            mma16816(d[2 * j],     al[s], bh[0], bh[1]);
            mma16816(d[2 * j + 1], al[s], bh[2], bh[3]);
        }
    }
}

// ---------------------------------------------------------------------------
// Kernel 1: xw0 precompute (FFMA2) — unchanged from R3
// ---------------------------------------------------------------------------
__global__ __launch_bounds__(256, 1) void input_gemm_kernel(
    const float* __restrict__ x, const float* __restrict__ Wih0,
    const float* __restrict__ bih0, const float* __restrict__ bhh0)
{
    __shared__ float Wt[IND * HID];
    __shared__ float xsT[IND * 64];
    __shared__ float bs[HID];

    const int tid = threadIdx.x;
    const int w = tid >> 5, lane = tid & 31;
    const int col0 = 16 * w, r0 = 2 * lane;

    for (int idx = tid; idx < HID * IND; idx += 256) {
        int j = idx / IND, d = idx - j * IND;
        Wt[d * HID + j] = Wih0[idx];
    }
    if (tid < HID) bs[tid] = bih0[tid] + bhh0[tid];
    __syncthreads();

    const unsigned aW = smaddr(Wt) + col0 * 4;
    const unsigned aB = smaddr(bs) + col0 * 4;

    for (int g = 0; g < IG_GROUPS; g++) {
        const int gr0 = blockIdx.x * IG_RPB + g * 64;
        __syncthreads();
        for (int idx = tid; idx < 64 * IND; idx += 256) {
            int r = idx / IND, d = idx - r * IND;
            xsT[d * 64 + r] = x[gr0 * IND + idx];
        }
        __syncthreads();

        u64 acc0[8], acc1[8];
        LDS2(acc0[0], acc0[1], aB);
        LDS2(acc0[2], acc0[3], aB + 16);
        LDS2(acc0[4], acc0[5], aB + 32);
        LDS2(acc0[6], acc0[7], aB + 48);
#pragma unroll
        for (int j = 0; j < 8; j++) acc1[j] = acc0[j];

#pragma unroll
        for (int d = 0; d < IND; d++) {
            float2 hp = *(const float2*)&xsT[d * 64 + r0];
            u64 ha, hb; DUP2(ha, hp.x); DUP2(hb, hp.y);
            u64 w0, w1, w2, w3, w4, w5, w6, w7;
            LDS2(w0, w1, aW + d * 512);
            LDS2(w2, w3, aW + d * 512 + 16);
            LDS2(w4, w5, aW + d * 512 + 32);
            LDS2(w6, w7, aW + d * 512 + 48);
            FMA2(acc0[0], ha, w0); FMA2(acc0[1], ha, w1);
            FMA2(acc0[2], ha, w2); FMA2(acc0[3], ha, w3);
            FMA2(acc0[4], ha, w4); FMA2(acc0[5], ha, w5);
            FMA2(acc0[6], ha, w6); FMA2(acc0[7], ha, w7);
            FMA2(acc1[0], hb, w0); FMA2(acc1[1], hb, w1);
            FMA2(acc1[2], hb, w2); FMA2(acc1[3], hb, w3);
            FMA2(acc1[4], hb, w4); FMA2(acc1[5], hb, w5);
            FMA2(acc1[6], hb, w6); FMA2(acc1[7], hb, w7);
        }

        float* dst0 = &g_xw0[(size_t)(gr0 + r0) * HID + col0];
        float* dst1 = dst0 + HID;
        STG2((u64)dst0,      acc0[0], acc0[1]);
        STG2((u64)dst0 + 16, acc0[2], acc0[3]);
        STG2((u64)dst0 + 32, acc0[4], acc0[5]);
        STG2((u64)dst0 + 48, acc0[6], acc0[7]);
        STG2((u64)dst1,      acc1[0], acc1[1]);
        STG2((u64)dst1 + 16, acc1[2], acc1[3]);
        STG2((u64)dst1 + 32, acc1[4], acc1[5]);
        STG2((u64)dst1 + 48, acc1[6], acc1[7]);
    }
}

// ---------------------------------------------------------------------------
// Kernel 2: mma.sync fused recurrence. 128 CTAs x 4 warps; each warp owns
// 16 batch rows; h0/h1 live as A-fragments in registers (no smem h, no
// syncthreads in the T loop). Weights bf16 hi/lo in smem, LDSM-loaded.
// ---------------------------------------------------------------------------
__global__ __launch_bounds__(128, 1) void rnn_mma_kernel(
    const float* __restrict__ Whh0, const float* __restrict__ Wih1,
    const float* __restrict__ Whh1, const float* __restrict__ bih1,
    const float* __restrict__ bhh1, const float* __restrict__ fcw,
    const float* __restrict__ fcb,  float* __restrict__ out)
{
    extern __shared__ char smem[];
    const int tid = threadIdx.x;
    const int wid = tid >> 5, lane = tid & 31;

    // ---- prologue: split weights into bf16 hi/lo padded tiles ----
    {
        const float* srcs[3] = { Whh0, Wih1, Whh1 };
#pragma unroll
        for (int m = 0; m < 3; m++) {
            char* hiT = smem + SM_W + (2 * m) * WTILE;
            char* loT = hiT + WTILE;
            const float* src = srcs[m];
            for (int idx = tid; idx < HID * HID; idx += 128) {
                int n = idx >> 7, k = idx & 127;
                float wv = src[idx];
                __nv_bfloat16 h = __float2bfloat16(wv);
                float hf = __bfloat162float(h);
                __nv_bfloat16 l = __float2bfloat16(wv - hf);
                uint32_t off = (uint32_t)n * WROW + (uint32_t)k * 2;
                *(__nv_bfloat16*)(hiT + off) = h;
                *(__nv_bfloat16*)(loT + off) = l;
            }
        }
        float* b1s = (float*)(smem + SM_B1);
        if (tid < HID) b1s[tid] = bih1[tid] + bhh1[tid];
        float* fcws = (float*)(smem + SM_FCW);
        for (int idx = tid; idx < NCLS * HID; idx += 128) fcws[idx] = fcw[idx];
        if (tid < NCLS) ((float*)(smem + SM_FCB))[tid] = fcb[tid];
    }
    __syncthreads();

    const uint32_t sb = smaddr(smem);
    // per-lane LDSM address component (mat0..3 of x4)
    const uint32_t laneoff =
        (uint32_t)((lane & 7) + ((lane >> 4) << 3)) * WROW +
        (uint32_t)(((lane >> 3) & 1) << 3) * 2;
    const uint32_t bW0h = sb + 0 * WTILE + laneoff;
    const uint32_t bW0l = sb + 1 * WTILE + laneoff;
    const uint32_t bW1h = sb + 2 * WTILE + laneoff;
    const uint32_t bW1l = sb + 3 * WTILE + laneoff;
    const uint32_t bW2h = sb + 4 * WTILE + laneoff;
    const uint32_t bW2l = sb + 5 * WTILE + laneoff;

    const float* b1s  = (const float*)(smem + SM_B1);
    const float* fcws = (const float*)(smem + SM_FCW);
    const float* fcbs = (const float*)(smem + SM_FCB);

    const int rowbase = blockIdx.x * 64 + wid * 16;  // this warp's 16 rows
    const int gr = lane >> 2;                        // group row 0..7
    const int m2 = (lane & 3) * 2;                   // col pair base

    // xw0 row pointers for rows (rowbase+gr) and (+8)
    const float* xr0base = g_xw0 + (size_t)(rowbase + gr) * T_STEPS * HID;
    const float* xr8base = xr0base + (size_t)8 * T_STEPS * HID;

    // h fragments (A-layout): [kstep][4], bf16x2 hi/lo
    uint32_t a0h[8][4], a0l[8][4], a1h[8][4], a1l[8][4];

    for (int t = 0; t < T_STEPS; t++) {
        // ---------------- layer 0 ----------------
        float d0[16][4];
#pragma unroll
        for (int i = 0; i < 16; i++)
#pragma unroll
            for (int q = 0; q < 4; q++) d0[i][q] = 0.0f;

        if (t > 0) gemm3(d0, a0h, a0l, bW0h, bW0l);

        // epilogue 0: h0 = tanh(d0 + xw0[t]); D-frag -> A-frag in registers
        const float* xr0 = xr0base + (size_t)t * HID;
        const float* xr8 = xr8base + (size_t)t * HID;
#pragma unroll
        for (int s = 0; s < 8; s++) {
            const int c = 16 * s + m2;
            float2 x00 = *(const float2*)(xr0 + c);
            float2 x80 = *(const float2*)(xr8 + c);
            float2 x01 = *(const float2*)(xr0 + c + 8);
            float2 x81 = *(const float2*)(xr8 + c + 8);
            cvt_pair(ftanh(d0[2*s][0] + x00.x), ftanh(d0[2*s][1] + x00.y),
                     a0h[s][0], a0l[s][0]);
            cvt_pair(ftanh(d0[2*s][2] + x80.x), ftanh(d0[2*s][3] + x80.y),
                     a0h[s][1], a0l[s][1]);
            cvt_pair(ftanh(d0[2*s+1][0] + x01.x), ftanh(d0[2*s+1][1] + x01.y),
                     a0h[s][2], a0l[s][2]);
            cvt_pair(ftanh(d0[2*s+1][2] + x81.x), ftanh(d0[2*s+1][3] + x81.y),
                     a0h[s][3], a0l[s][3]);
        }

        // ---------------- layer 1 ----------------
        float d1[16][4];
#pragma unroll
        for (int i = 0; i < 16; i++)
#pragma unroll
            for (int q = 0; q < 4; q++) d1[i][q] = 0.0f;

        gemm3(d1, a0h, a0l, bW1h, bW1l);
        if (t > 0) gemm3(d1, a1h, a1l, bW2h, bW2l);

        if (t + 1 < T_STEPS) {
            // epilogue 1: h1 = tanh(d1 + b1)
#pragma unroll
            for (int s = 0; s < 8; s++) {
                const int c = 16 * s + m2;
                float2 bb0 = *(const float2*)(b1s + c);
                float2 bb1 = *(const float2*)(b1s + c + 8);
                cvt_pair(ftanh(d1[2*s][0] + bb0.x), ftanh(d1[2*s][1] + bb0.y),
                         a1h[s][0], a1l[s][0]);
                cvt_pair(ftanh(d1[2*s][2] + bb0.x), ftanh(d1[2*s][3] + bb0.y),
                         a1h[s][1], a1l[s][1]);
                cvt_pair(ftanh(d1[2*s+1][0] + bb1.x), ftanh(d1[2*s+1][1] + bb1.y),
                         a1h[s][2], a1l[s][2]);
                cvt_pair(ftanh(d1[2*s+1][2] + bb1.x), ftanh(d1[2*s+1][3] + bb1.y),
                         a1h[s][3], a1l[s][3]);
            }
        } else {
            // ---------------- FC head on final h1 ----------------
            float facc0[NCLS], facc1[NCLS];
#pragma unroll
            for (int cl = 0; cl < NCLS; cl++) { facc0[cl] = 0.0f; facc1[cl] = 0.0f; }
#pragma unroll
            for (int s = 0; s < 8; s++) {
                const int c = 16 * s + m2;
                float2 bb0 = *(const float2*)(b1s + c);
                float2 bb1 = *(const float2*)(b1s + c + 8);
                float h00 = ftanh(d1[2*s][0] + bb0.x);
                float h01 = ftanh(d1[2*s][1] + bb0.y);
                float h02 = ftanh(d1[2*s+1][0] + bb1.x);
                float h03 = ftanh(d1[2*s+1][1] + bb1.y);
                float h80 = ftanh(d1[2*s][2] + bb0.x);
                float h81 = ftanh(d1[2*s][3] + bb0.y);
                float h82 = ftanh(d1[2*s+1][2] + bb1.x);
                float h83 = ftanh(d1[2*s+1][3] + bb1.y);
#pragma unroll
                for (int cl = 0; cl < NCLS; cl++) {
                    const float* fr = fcws + cl * HID + c;
                    facc0[cl] += h00 * fr[0] + h01 * fr[1] + h02 * fr[8] + h03 * fr[9];
                    facc1[cl] += h80 * fr[0] + h81 * fr[1] + h82 * fr[8] + h83 * fr[9];
                }
            }
            // reduce across the 4 lanes of each row-quad
#pragma unroll
            for (int cl = 0; cl < NCLS; cl++) {
                facc0[cl] += __shfl_xor_sync(0xffffffff, facc0[cl], 1);
                facc0[cl] += __shfl_xor_sync(0xffffffff, facc0[cl], 2);
                facc1[cl] += __shfl_xor_sync(0xffffffff, facc1[cl], 1);
                facc1[cl] += __shfl_xor_sync(0xffffffff, facc1[cl], 2);
            }
            if ((lane & 3) == 0) {
                float* o0 = out + (size_t)(rowbase + gr) * NCLS;
                float* o8 = o0 + (size_t)8 * NCLS;
#pragma unroll
                for (int cl = 0; cl < NCLS; cl++) {
                    o0[cl] = facc0[cl] + fcbs[cl];
                    o8[cl] = facc1[cl] + fcbs[cl];
                }
            }
        }
    }
}

// ---------------------------------------------------------------------------
extern "C" void kernel_launch(void* const* d_in, const int* in_sizes, int n_in,
                              void* d_out, int out_size) {
    const float* x    = (const float*)d_in[0];
    const float* Wih0 = (const float*)d_in[1];
    const float* Whh0 = (const float*)d_in[2];
    const float* bih0 = (const float*)d_in[3];
    const float* bhh0 = (const float*)d_in[4];
    const float* Wih1 = (const float*)d_in[5];
    const float* Whh1 = (const float*)d_in[6];
    const float* bih1 = (const float*)d_in[7];
    const float* bhh1 = (const float*)d_in[8];
    const float* fcw  = (const float*)d_in[9];
    const float* fcb  = (const float*)d_in[10];
    float* out = (float*)d_out;

    cudaFuncSetAttribute(rnn_mma_kernel,
                         cudaFuncAttributeMaxDynamicSharedMemorySize, SMEM_TOTAL);

    input_gemm_kernel<<<(BATCH * T_STEPS) / IG_RPB, 256>>>(x, Wih0, bih0, bhh0);
    rnn_mma_kernel<<<BATCH / 64, 128, SMEM_TOTAL>>>(Whh0, Wih1, Whh1,
                                                    bih1, bhh1, fcw, fcb, out);
}

// round 8
// speedup vs baseline: 3.4728x; 1.2585x over previous
#include <cuda_runtime.h>
#include <cuda_bf16.h>
#include <cstdint>

#define T_STEPS 28
#define HID 128
#define IND 28
#define NCLS 10
#define BATCH 8192
#define IG_GROUPS 4
#define IG_RPB (64 * IG_GROUPS)

typedef unsigned long long u64;

// 112 MB scratch: precomputed layer-0 input GEMM (+ fused biases)
__device__ float g_xw0[BATCH * T_STEPS * HID];

// ---------------- packed fp32x2 helpers (input gemm) ----------------
#define FMA2(acc, a, b) \
    asm("fma.rn.f32x2 %0, %1, %2, %0;" : "+l"(acc) : "l"(a), "l"(b))
#define DUP2(d, s) \
    asm("mov.b64 %0, {%1, %1};" : "=l"(d) : "f"(s))
#define LDS2(a, b, addr) \
    asm("ld.shared.v2.u64 {%0, %1}, [%2];" : "=l"(a), "=l"(b) : "r"(addr))
#define STG2(p, a, b) \
    asm("st.global.v2.u64 [%0], {%1, %2};" :: "l"(p), "l"(a), "l"(b))

__device__ __forceinline__ float ftanh(float x) {
    float e = __expf(2.0f * x);
    return 1.0f - __fdividef(2.0f, e + 1.0f);
}
__device__ __forceinline__ unsigned smaddr(const void* p) {
    return (unsigned)__cvta_generic_to_shared(p);
}

// ---------------- mma.sync helpers ----------------
__device__ __forceinline__ void ldsm4(uint32_t* r, uint32_t a) {
    asm volatile("ldmatrix.sync.aligned.m8n8.x4.shared.b16 {%0,%1,%2,%3}, [%4];"
                 : "=r"(r[0]), "=r"(r[1]), "=r"(r[2]), "=r"(r[3]) : "r"(a));
}
__device__ __forceinline__ void mma16816(float* d, const uint32_t* a,
                                         uint32_t b0, uint32_t b1) {
    asm volatile("mma.sync.aligned.m16n8k16.row.col.f32.bf16.bf16.f32 "
                 "{%0,%1,%2,%3}, {%4,%5,%6,%7}, {%8,%9}, {%0,%1,%2,%3};"
                 : "+f"(d[0]), "+f"(d[1]), "+f"(d[2]), "+f"(d[3])
                 : "r"(a[0]), "r"(a[1]), "r"(a[2]), "r"(a[3]), "r"(b0), "r"(b1));
}
__device__ __forceinline__ uint32_t pack2(float v0, float v1) {
    uint32_t r;
    asm("cvt.rn.bf16x2.f32 %0, %1, %2;" : "=r"(r) : "f"(v1), "f"(v0));
    return r;
}
__device__ __forceinline__ void cvt_pair(float v0, float v1,
                                         uint32_t& hi, uint32_t& lo) {
    uint32_t hp = pack2(v0, v1);
    float e0 = __uint_as_float(hp << 16);
    float e1 = __uint_as_float(hp & 0xffff0000u);
    hi = hp;
    lo = pack2(v0 - e0, v1 - e1);
}
#define STS32(a, v) asm volatile("st.shared.b32 [%0], %1;" :: "r"(a), "r"(v) : "memory")
#define BARG(id) asm volatile("bar.sync %0, %1;" :: "r"(id), "r"(64) : "memory")

// ---- weight tiles: [n][k] bf16, 128 rows x 256B, XOR-swizzled 16B chunks ----
#define WROWB 256
#define WTILE2 (128 * WROWB)          // 32768 B
#define SM_W   0                      // 6 tiles: W0h W0l W1h W1l W2h W2l
#define SM_HX  (6 * WTILE2)           // 196608: 4 group bufs x 8192 (hi@0, lo@4096)
#define SM_B1  (SM_HX + 4 * 8192)     // 229376: 128 f32
#define SMEM_TOTAL (SM_B1 + 512)      // 229888

// swizzled byte offset of bf16 (n,k) in a weight tile
__device__ __forceinline__ uint32_t wtile_off2(int n, int k) {
    return (uint32_t)n * WROWB + ((((uint32_t)k >> 3) ^ ((uint32_t)n & 7)) << 4)
           + ((uint32_t)k & 7) * 2;
}

// 3-term split-bf16 half-GEMM: d[8][4] += A(split) @ W_half(split)^T, K=128, N=64
// baseHi/baseLo already include (64u + rowB)*256; kb/xr are lane constants.
__device__ __forceinline__ void gemm3h(float (*d)[4],
                                       const uint32_t (*ah)[4],
                                       const uint32_t (*al)[4],
                                       uint32_t baseHi, uint32_t baseLo,
                                       int kb, int xr) {
#pragma unroll
    for (int s = 0; s < 8; s++) {
        const uint32_t coff = (uint32_t)(((2 * s + kb) ^ xr) << 4);
#pragma unroll
        for (int j = 0; j < 4; j++) {
            uint32_t bh[4], bl[4];
            ldsm4(bh, baseHi + j * 4096 + coff);
            ldsm4(bl, baseLo + j * 4096 + coff);
            mma16816(d[2 * j],     ah[s], bh[0], bh[1]);
            mma16816(d[2 * j + 1], ah[s], bh[2], bh[3]);
            mma16816(d[2 * j],     ah[s], bl[0], bl[1]);
            mma16816(d[2 * j + 1], ah[s], bl[2], bl[3]);
            mma16816(d[2 * j],     al[s], bh[0], bh[1]);
            mma16816(d[2 * j + 1], al[s], bh[2], bh[3]);
        }
    }
}

// load full-K A fragments (8 k-steps) from a 16x128 bf16 exchange tile
__device__ __forceinline__ void ldA(uint32_t (*f)[4], uint32_t base, int kb, int xr) {
#pragma unroll
    for (int s = 0; s < 8; s++)
        ldsm4(f[s], base + (uint32_t)(((2 * s + kb) ^ xr) << 4));
}

// ---------------------------------------------------------------------------
// Kernel 1: xw0 precompute (FFMA2) — unchanged
// ---------------------------------------------------------------------------
__global__ __launch_bounds__(256, 1) void input_gemm_kernel(
    const float* __restrict__ x, const float* __restrict__ Wih0,
    const float* __restrict__ bih0, const float* __restrict__ bhh0)
{
    __shared__ float Wt[IND * HID];
    __shared__ float xsT[IND * 64];
    __shared__ float bs[HID];

    const int tid = threadIdx.x;
    const int w = tid >> 5, lane = tid & 31;
    const int col0 = 16 * w, r0 = 2 * lane;

    for (int idx = tid; idx < HID * IND; idx += 256) {
        int j = idx / IND, d = idx - j * IND;
        Wt[d * HID + j] = Wih0[idx];
    }
    if (tid < HID) bs[tid] = bih0[tid] + bhh0[tid];
    __syncthreads();

    const unsigned aW = smaddr(Wt) + col0 * 4;
    const unsigned aB = smaddr(bs) + col0 * 4;

    for (int g = 0; g < IG_GROUPS; g++) {
        const int gr0 = blockIdx.x * IG_RPB + g * 64;
        __syncthreads();
        for (int idx = tid; idx < 64 * IND; idx += 256) {
            int r = idx / IND, d = idx - r * IND;
            xsT[d * 64 + r] = x[gr0 * IND + idx];
        }
        __syncthreads();

        u64 acc0[8], acc1[8];
        LDS2(acc0[0], acc0[1], aB);
        LDS2(acc0[2], acc0[3], aB + 16);
        LDS2(acc0[4], acc0[5], aB + 32);
        LDS2(acc0[6], acc0[7], aB + 48);
#pragma unroll
        for (int j = 0; j < 8; j++) acc1[j] = acc0[j];

#pragma unroll
        for (int d = 0; d < IND; d++) {
            float2 hp = *(const float2*)&xsT[d * 64 + r0];
            u64 ha, hb; DUP2(ha, hp.x); DUP2(hb, hp.y);
            u64 w0, w1, w2, w3, w4, w5, w6, w7;
            LDS2(w0, w1, aW + d * 512);
            LDS2(w2, w3, aW + d * 512 + 16);
            LDS2(w4, w5, aW + d * 512 + 32);
            LDS2(w6, w7, aW + d * 512 + 48);
            FMA2(acc0[0], ha, w0); FMA2(acc0[1], ha, w1);
            FMA2(acc0[2], ha, w2); FMA2(acc0[3], ha, w3);
            FMA2(acc0[4], ha, w4); FMA2(acc0[5], ha, w5);
            FMA2(acc0[6], ha, w6); FMA2(acc0[7], ha, w7);
            FMA2(acc1[0], hb, w0); FMA2(acc1[1], hb, w1);
            FMA2(acc1[2], hb, w2); FMA2(acc1[3], hb, w3);
            FMA2(acc1[4], hb, w4); FMA2(acc1[5], hb, w5);
            FMA2(acc1[6], hb, w6); FMA2(acc1[7], hb, w7);
        }

        float* dst0 = &g_xw0[(size_t)(gr0 + r0) * HID + col0];
        float* dst1 = dst0 + HID;
        STG2((u64)dst0,      acc0[0], acc0[1]);
        STG2((u64)dst0 + 16, acc0[2], acc0[3]);
        STG2((u64)dst0 + 32, acc0[4], acc0[5]);
        STG2((u64)dst0 + 48, acc0[6], acc0[7]);
        STG2((u64)dst1,      acc1[0], acc1[1]);
        STG2((u64)dst1 + 16, acc1[2], acc1[3]);
        STG2((u64)dst1 + 32, acc1[4], acc1[5]);
        STG2((u64)dst1 + 48, acc1[6], acc1[7]);
    }
}

// ---------------------------------------------------------------------------
// Kernel 2: mma.sync fused recurrence, N-split warp pairs.
// 128 CTAs x 8 warps; pair g owns 16 batch rows; warp u in {0,1} owns 64
// hidden cols. h exchanged as bf16 hi/lo via per-pair smem tiles + named bars.
// ---------------------------------------------------------------------------
__global__ __launch_bounds__(256, 1) void rnn_mma_kernel(
    const float* __restrict__ Whh0, const float* __restrict__ Wih1,
    const float* __restrict__ Whh1, const float* __restrict__ bih1,
    const float* __restrict__ bhh1, const float* __restrict__ fcw,
    const float* __restrict__ fcb,  float* __restrict__ out)
{
    extern __shared__ char smem[];
    const int tid = threadIdx.x;
    const int wid = tid >> 5, lane = tid & 31;
    const int g = wid >> 1, u = wid & 1;

    // ---- prologue: split weights into bf16 hi/lo swizzled 256B-row tiles ----
    {
        const float* srcs[3] = { Whh0, Wih1, Whh1 };
#pragma unroll
        for (int m = 0; m < 3; m++) {
            char* hiT = smem + SM_W + (2 * m) * WTILE2;
            char* loT = hiT + WTILE2;
            const float* src = srcs[m];
            for (int idx = tid; idx < HID * HID; idx += 256) {
                int n = idx >> 7, k = idx & 127;
                float wv = src[idx];
                __nv_bfloat16 h = __float2bfloat16(wv);
                float hf = __bfloat162float(h);
                __nv_bfloat16 l = __float2bfloat16(wv - hf);
                uint32_t off = wtile_off2(n, k);
                *(__nv_bfloat16*)(hiT + off) = h;
                *(__nv_bfloat16*)(loT + off) = l;
            }
        }
        float* b1s = (float*)(smem + SM_B1);
        if (tid < HID) b1s[tid] = bih1[tid] + bhh1[tid];
    }
    __syncthreads();

    const uint32_t sb = smaddr(smem);
    const int xr  = lane & 7;
    const int kbB = (lane >> 3) & 1;
    const int rowB = (lane & 7) + ((lane >> 4) << 3);
    const int kbA = (lane >> 4) & 1;
    const int rowA = (lane & 7) + (((lane >> 3) & 1) << 3);
    const int gr = lane >> 2, m2 = (lane & 3) * 2;

    // weight fragment base addresses (include this warp's 64-col half)
    const uint32_t wb0h = sb + 0 * WTILE2 + (uint32_t)(u * 64 + rowB) * WROWB;
    const uint32_t wb0l = sb + 1 * WTILE2 + (uint32_t)(u * 64 + rowB) * WROWB;
    const uint32_t wb1h = sb + 2 * WTILE2 + (uint32_t)(u * 64 + rowB) * WROWB;
    const uint32_t wb1l = sb + 3 * WTILE2 + (uint32_t)(u * 64 + rowB) * WROWB;
    const uint32_t wb2h = sb + 4 * WTILE2 + (uint32_t)(u * 64 + rowB) * WROWB;
    const uint32_t wb2l = sb + 5 * WTILE2 + (uint32_t)(u * 64 + rowB) * WROWB;

    // exchange buffer (per pair): hi tile @0, lo tile @4096
    const uint32_t hbuf = sb + SM_HX + (uint32_t)g * 8192;
    const uint32_t hAhi = hbuf + (uint32_t)rowA * WROWB;
    const uint32_t hAlo = hAhi + 4096;
    // h-write base: row gr, col byte m2*2 (chunk term added per nb)
    const uint32_t hw = hbuf + (uint32_t)gr * WROWB + (uint32_t)m2 * 2;

    const float* b1s = (const float*)(smem + SM_B1);
    const int barid = 1 + g;

    // xw0 row pointers for rows (base+gr) and (base+gr+8)
    const int rowbase = blockIdx.x * 64 + g * 16;
    const float* xb0 = g_xw0 + (size_t)(rowbase + gr) * T_STEPS * HID;
    const float* xb8 = xb0 + (size_t)8 * T_STEPS * HID;

    // h fragments (full K): [kstep][4]
    uint32_t a0h[8][4], a0l[8][4], a1h[8][4], a1l[8][4];
#pragma unroll
    for (int s = 0; s < 8; s++)
#pragma unroll
        for (int q = 0; q < 4; q++) { a0h[s][q] = 0; a0l[s][q] = 0; a1h[s][q] = 0; a1l[s][q] = 0; }

    float2 xpf[16];
    {   // prefetch x for t=0
#pragma unroll
        for (int nb = 0; nb < 8; nb++) {
            int cg = u * 64 + nb * 8 + m2;
            xpf[2 * nb]     = *(const float2*)(xb0 + cg);
            xpf[2 * nb + 1] = *(const float2*)(xb8 + cg);
        }
    }

#pragma unroll 1
    for (int t = 0; t < T_STEPS; t++) {
        // ---------------- layer 0 ----------------
        float d0[8][4];
#pragma unroll
        for (int i = 0; i < 8; i++)
#pragma unroll
            for (int q = 0; q < 4; q++) d0[i][q] = 0.0f;

        if (t > 0) gemm3h(d0, a0h, a0l, wb0h, wb0l, kbB, xr);

        // epilogue 0: h0 = tanh(d0 + xw0_t) -> write bf16 hi/lo halves to smem
#pragma unroll
        for (int nb = 0; nb < 8; nb++) {
            float v0 = ftanh(d0[nb][0] + xpf[2 * nb].x);
            float v1 = ftanh(d0[nb][1] + xpf[2 * nb].y);
            float v2 = ftanh(d0[nb][2] + xpf[2 * nb + 1].x);
            float v3 = ftanh(d0[nb][3] + xpf[2 * nb + 1].y);
            uint32_t hi0, lo0, hi8, lo8;
            cvt_pair(v0, v1, hi0, lo0);
            cvt_pair(v2, v3, hi8, lo8);
            uint32_t off = (uint32_t)(((u * 8 + nb) ^ gr) << 4);
            STS32(hw + off,        hi0);
            STS32(hw + off + 2048, hi8);   // row gr+8
            STS32(hw + off + 4096, lo0);
            STS32(hw + off + 6144, lo8);
        }
        BARG(barid);
        ldA(a0h, hAhi, kbA, xr);
        ldA(a0l, hAlo, kbA, xr);
        BARG(barid);

        // prefetch next step's x (covered by layer-1 MMA latency)
        if (t + 1 < T_STEPS) {
#pragma unroll
            for (int nb = 0; nb < 8; nb++) {
                int cg = u * 64 + nb * 8 + m2;
                xpf[2 * nb]     = *(const float2*)(xb0 + (size_t)(t + 1) * HID + cg);
                xpf[2 * nb + 1] = *(const float2*)(xb8 + (size_t)(t + 1) * HID + cg);
            }
        }

        // ---------------- layer 1 ----------------
        float d1[8][4];
#pragma unroll
        for (int i = 0; i < 8; i++)
#pragma unroll
            for (int q = 0; q < 4; q++) d1[i][q] = 0.0f;

        gemm3h(d1, a0h, a0l, wb1h, wb1l, kbB, xr);
        if (t > 0) gemm3h(d1, a1h, a1l, wb2h, wb2l, kbB, xr);

        if (t + 1 < T_STEPS) {
            // epilogue 1: h1 = tanh(d1 + b1) -> exchange
#pragma unroll
            for (int nb = 0; nb < 8; nb++) {
                int cg = u * 64 + nb * 8 + m2;
                float2 bb = *(const float2*)(b1s + cg);
                float v0 = ftanh(d1[nb][0] + bb.x);
                float v1 = ftanh(d1[nb][1] + bb.y);
                float v2 = ftanh(d1[nb][2] + bb.x);
                float v3 = ftanh(d1[nb][3] + bb.y);
                uint32_t hi0, lo0, hi8, lo8;
                cvt_pair(v0, v1, hi0, lo0);
                cvt_pair(v2, v3, hi8, lo8);
                uint32_t off = (uint32_t)(((u * 8 + nb) ^ gr) << 4);
                STS32(hw + off,        hi0);
                STS32(hw + off + 2048, hi8);
                STS32(hw + off + 4096, lo0);
                STS32(hw + off + 6144, lo8);
            }
            BARG(barid);
            ldA(a1h, hAhi, kbA, xr);
            ldA(a1l, hAlo, kbA, xr);
            BARG(barid);
        } else {
            // ---------------- FC head ----------------
            __syncthreads();      // exchange buffers now free CTA-wide
            float* fstage  = (float*)(smem + SM_HX + 3 * 8192 + 2048);
            float* fbstage = (float*)(smem + SM_HX + 3 * 8192 + 7680);
            for (int i = tid; i < NCLS * HID; i += 256) fstage[i] = fcw[i];
            if (tid < NCLS) fbstage[tid] = fcb[tid];
            __syncthreads();

            float facc[2][NCLS];
#pragma unroll
            for (int r = 0; r < 2; r++)
#pragma unroll
                for (int cl = 0; cl < NCLS; cl++) facc[r][cl] = 0.0f;

#pragma unroll
            for (int nb = 0; nb < 8; nb++) {
                int cg = u * 64 + nb * 8 + m2;
                float2 bb = *(const float2*)(b1s + cg);
                float h0v = ftanh(d1[nb][0] + bb.x);
                float h1v = ftanh(d1[nb][1] + bb.y);
                float h8v = ftanh(d1[nb][2] + bb.x);
                float h9v = ftanh(d1[nb][3] + bb.y);
#pragma unroll
                for (int cl = 0; cl < NCLS; cl++) {
                    float2 fw = *(const float2*)(fstage + cl * HID + cg);
                    facc[0][cl] += h0v * fw.x + h1v * fw.y;
                    facc[1][cl] += h8v * fw.x + h9v * fw.y;
                }
            }
#pragma unroll
            for (int r = 0; r < 2; r++)
#pragma unroll
                for (int cl = 0; cl < NCLS; cl++) {
                    facc[r][cl] += __shfl_xor_sync(0xffffffff, facc[r][cl], 1);
                    facc[r][cl] += __shfl_xor_sync(0xffffffff, facc[r][cl], 2);
                }

            float* part = (float*)(smem + SM_HX + g * 8192);   // [2 halves][16 rows][10]
            if ((lane & 3) == 0) {
#pragma unroll
                for (int cl = 0; cl < NCLS; cl++) {
                    part[(u * 16 + gr) * NCLS + cl]     = facc[0][cl];
                    part[(u * 16 + gr + 8) * NCLS + cl] = facc[1][cl];
                }
            }
            BARG(barid);
            if (u == 0 && lane < 16) {
                const int grow = rowbase + lane;
#pragma unroll
                for (int cl = 0; cl < NCLS; cl++)
                    out[(size_t)grow * NCLS + cl] =
                        part[lane * NCLS + cl] + part[(16 + lane) * NCLS + cl] + fbstage[cl];
            }
        }
    }
}

// ---------------------------------------------------------------------------
extern "C" void kernel_launch(void* const* d_in, const int* in_sizes, int n_in,
                              void* d_out, int out_size) {
    const float* x    = (const float*)d_in[0];
    const float* Wih0 = (const float*)d_in[1];
    const float* Whh0 = (const float*)d_in[2];
    const float* bih0 = (const float*)d_in[3];
    const float* bhh0 = (const float*)d_in[4];
    const float* Wih1 = (const float*)d_in[5];
    const float* Whh1 = (const float*)d_in[6];
    const float* bih1 = (const float*)d_in[7];
    const float* bhh1 = (const float*)d_in[8];
    const float* fcw  = (const float*)d_in[9];
    const float* fcb  = (const float*)d_in[10];
    float* out = (float*)d_out;

    cudaFuncSetAttribute(rnn_mma_kernel,
                         cudaFuncAttributeMaxDynamicSharedMemorySize, SMEM_TOTAL);

    input_gemm_kernel<<<(BATCH * T_STEPS) / IG_RPB, 256>>>(x, Wih0, bih0, bhh0);
    rnn_mma_kernel<<<BATCH / 64, 256, SMEM_TOTAL>>>(Whh0, Wih1, Whh1,
                                                    bih1, bhh1, fcw, fcb, out);
}